// round 1
// baseline (speedup 1.0000x reference)
#include <cuda_runtime.h>
#include <math.h>

#define T_  12
#define E_  8192
#define H_  256
#define V_  800
#define B_  256
#define NB_ 8
#define M_  (T_*E_)   // 98304 messages; h has 1+M rows (row 0 = pad)

// ---------------- scratch (static device arrays; no allocs allowed) ----------
__device__ float g_hU[(size_t)(M_+1)*H_];   // h @ Ur, maintained incrementally
__device__ float g_sumh[(size_t)E_*H_];     // per-step sum of neighbor h
__device__ float g_sumg[(size_t)E_*H_];     // per-step sum of gated neighbor h
__device__ float g_Ez[(size_t)V_*H_];       // embedding @ Wz[0:H]
__device__ float g_Er[(size_t)V_*H_];       // embedding @ Wr
__device__ float g_Eh[(size_t)V_*H_];       // embedding @ Wh[0:H]
__device__ float g_Eo[(size_t)V_*H_];       // embedding @ Wo[0:H]
__device__ float g_rootsum[(size_t)B_*H_];

__device__ __forceinline__ float sigf(float x) { return 1.0f / (1.0f + __expf(-x)); }

// ---------------- init: zero pad rows -----------------------------------------
__global__ void init_zero(float* __restrict__ h)
{
    int c = threadIdx.x;     // 256 threads
    h[c]    = 0.0f;          // h row 0
    g_hU[c] = 0.0f;          // hU row 0
}

// ---------------- generic tiled GEMM: C[M,256] = A[M,256] @ B[256,256] --------
// 64x64 tile, BK=16, 256 threads, 4x4 microtile. Rows >= Mrows zero-padded.
__global__ void gemm256(const float* __restrict__ A, const float* __restrict__ Bw,
                        float* __restrict__ C, int Mrows)
{
    __shared__ float As[16][64];
    __shared__ float Bs[16][64];

    const int tid = threadIdx.x;
    const int tx = tid & 15, ty = tid >> 4;
    const int rowBase = blockIdx.y * 64;
    const int colBase = blockIdx.x * 64;

    const int lm  = tid >> 2;         // A-load row within tile (0..63)
    const int lk  = (tid & 3) * 4;    // A-load k offset (0,4,8,12)
    const int blk = tid >> 4;         // B-load k row (0..15)
    const int bln = (tid & 15) * 4;   // B-load col offset

    float acc[4][4] = {};

    for (int kb = 0; kb < 256; kb += 16) {
        int ar = rowBase + lm;
        float4 av = make_float4(0.f, 0.f, 0.f, 0.f);
        if (ar < Mrows)
            av = *reinterpret_cast<const float4*>(&A[(size_t)ar * 256 + kb + lk]);
        As[lk + 0][lm] = av.x; As[lk + 1][lm] = av.y;
        As[lk + 2][lm] = av.z; As[lk + 3][lm] = av.w;

        float4 bv = *reinterpret_cast<const float4*>(&Bw[(size_t)(kb + blk) * 256 + colBase + bln]);
        *reinterpret_cast<float4*>(&Bs[blk][bln]) = bv;
        __syncthreads();

#pragma unroll
        for (int k = 0; k < 16; ++k) {
            float4 a4 = *reinterpret_cast<const float4*>(&As[k][ty * 4]);
            float4 b4 = *reinterpret_cast<const float4*>(&Bs[k][tx * 4]);
            float aa[4] = {a4.x, a4.y, a4.z, a4.w};
            float bb[4] = {b4.x, b4.y, b4.z, b4.w};
#pragma unroll
            for (int i = 0; i < 4; ++i)
#pragma unroll
                for (int j = 0; j < 4; ++j)
                    acc[i][j] += aa[i] * bb[j];
        }
        __syncthreads();
    }

#pragma unroll
    for (int i = 0; i < 4; ++i) {
        int r = rowBase + ty * 4 + i;
        if (r < Mrows)
            *reinterpret_cast<float4*>(&C[(size_t)r * 256 + colBase + tx * 4]) =
                make_float4(acc[i][0], acc[i][1], acc[i][2], acc[i][3]);
    }
}

// ---------------- per-step gather: sum_h and sum_gated ------------------------
// r = sigmoid( Er[xid] + bur + hU[j] ), sum_gated = sum_j r * h[j]
__global__ void gather_step(const float* __restrict__ h,     // d_out base (h rows)
                            const int*   __restrict__ nei,   // nei_idx + t*E*NB
                            const int*   __restrict__ xids,  // x_ids + t*E
                            const float* __restrict__ bur)
{
    const int e = blockIdx.x;
    const int c = threadIdx.x;   // 256 threads, one H column each
    __shared__ int sj[NB_];
    if (c < NB_) sj[c] = nei[e * NB_ + c];
    __syncthreads();

    const int xid = xids[e];
    const float base = g_Er[(size_t)xid * 256 + c] + bur[c];

    float sh = 0.f, sg = 0.f;
#pragma unroll
    for (int n = 0; n < NB_; ++n) {
        const int j = sj[n];
        const float hv = h[(size_t)j * 256 + c];
        const float uv = g_hU[(size_t)j * 256 + c];
        sh += hv;
        sg += sigf(base + uv) * hv;
    }
    g_sumh[(size_t)e * 256 + c] = sh;
    g_sumg[(size_t)e * 256 + c] = sg;
}

// ---------------- fused dual GEMM + GRU epilogue ------------------------------
// acc1 = sum_h @ Wz_h ; acc2 = sum_gated @ Wh_h
// z = sigmoid(Ez[xid] + bz + acc1) ; p = tanh(Eh[xid] + bh + acc2)
// new_h = (1-z)*sum_h + z*p   (written directly into d_out rows)
__global__ void zpre_gemm(const float* __restrict__ Wzh, const float* __restrict__ Whh,
                          const float* __restrict__ bz,  const float* __restrict__ bh,
                          const int*   __restrict__ xids,   // x_ids + t*E
                          float*       __restrict__ hout)   // d_out + (1+t*E)*H
{
    __shared__ float As[16][64];
    __shared__ float Bs[16][64];

    const int tid = threadIdx.x;
    const int tx = tid & 15, ty = tid >> 4;
    const int rowBase = blockIdx.y * 64;
    const int colBase = blockIdx.x * 64;

    const int lm  = tid >> 2;
    const int lk  = (tid & 3) * 4;
    const int blk = tid >> 4;
    const int bln = (tid & 15) * 4;

    float acc1[4][4] = {};
    float acc2[4][4] = {};

    // pass 1: sum_h @ Wz_h
    for (int kb = 0; kb < 256; kb += 16) {
        float4 av = *reinterpret_cast<const float4*>(&g_sumh[(size_t)(rowBase + lm) * 256 + kb + lk]);
        As[lk + 0][lm] = av.x; As[lk + 1][lm] = av.y;
        As[lk + 2][lm] = av.z; As[lk + 3][lm] = av.w;
        float4 bv = *reinterpret_cast<const float4*>(&Wzh[(size_t)(kb + blk) * 256 + colBase + bln]);
        *reinterpret_cast<float4*>(&Bs[blk][bln]) = bv;
        __syncthreads();
#pragma unroll
        for (int k = 0; k < 16; ++k) {
            float4 a4 = *reinterpret_cast<const float4*>(&As[k][ty * 4]);
            float4 b4 = *reinterpret_cast<const float4*>(&Bs[k][tx * 4]);
            float aa[4] = {a4.x, a4.y, a4.z, a4.w};
            float bb[4] = {b4.x, b4.y, b4.z, b4.w};
#pragma unroll
            for (int i = 0; i < 4; ++i)
#pragma unroll
                for (int j = 0; j < 4; ++j)
                    acc1[i][j] += aa[i] * bb[j];
        }
        __syncthreads();
    }

    // pass 2: sum_gated @ Wh_h
    for (int kb = 0; kb < 256; kb += 16) {
        float4 av = *reinterpret_cast<const float4*>(&g_sumg[(size_t)(rowBase + lm) * 256 + kb + lk]);
        As[lk + 0][lm] = av.x; As[lk + 1][lm] = av.y;
        As[lk + 2][lm] = av.z; As[lk + 3][lm] = av.w;
        float4 bv = *reinterpret_cast<const float4*>(&Whh[(size_t)(kb + blk) * 256 + colBase + bln]);
        *reinterpret_cast<float4*>(&Bs[blk][bln]) = bv;
        __syncthreads();
#pragma unroll
        for (int k = 0; k < 16; ++k) {
            float4 a4 = *reinterpret_cast<const float4*>(&As[k][ty * 4]);
            float4 b4 = *reinterpret_cast<const float4*>(&Bs[k][tx * 4]);
            float aa[4] = {a4.x, a4.y, a4.z, a4.w};
            float bb[4] = {b4.x, b4.y, b4.z, b4.w};
#pragma unroll
            for (int i = 0; i < 4; ++i)
#pragma unroll
                for (int j = 0; j < 4; ++j)
                    acc2[i][j] += aa[i] * bb[j];
        }
        __syncthreads();
    }

    // epilogue
#pragma unroll
    for (int i = 0; i < 4; ++i) {
        const int r = rowBase + ty * 4 + i;
        const int xid = xids[r];
        const int n = colBase + tx * 4;
        float ez[4], eh[4], bzv[4], bhv[4], sh[4], o[4];
        *reinterpret_cast<float4*>(ez)  = *reinterpret_cast<const float4*>(&g_Ez[(size_t)xid * 256 + n]);
        *reinterpret_cast<float4*>(eh)  = *reinterpret_cast<const float4*>(&g_Eh[(size_t)xid * 256 + n]);
        *reinterpret_cast<float4*>(bzv) = *reinterpret_cast<const float4*>(&bz[n]);
        *reinterpret_cast<float4*>(bhv) = *reinterpret_cast<const float4*>(&bh[n]);
        *reinterpret_cast<float4*>(sh)  = *reinterpret_cast<const float4*>(&g_sumh[(size_t)r * 256 + n]);
#pragma unroll
        for (int j = 0; j < 4; ++j) {
            float z = sigf(ez[j] + bzv[j] + acc1[i][j]);
            float p = tanhf(eh[j] + bhv[j] + acc2[i][j]);
            o[j] = (1.0f - z) * sh[j] + z * p;
        }
        *reinterpret_cast<float4*>(&hout[(size_t)r * 256 + n]) = *reinterpret_cast<const float4*>(o);
    }
}

// ---------------- root aggregate ---------------------------------------------
__global__ void root_gather(const float* __restrict__ h, const int* __restrict__ rnei)
{
    const int b = blockIdx.x;
    const int c = threadIdx.x;
    __shared__ int sj[NB_];
    if (c < NB_) sj[c] = rnei[b * NB_ + c];
    __syncthreads();
    float s = 0.f;
#pragma unroll
    for (int n = 0; n < NB_; ++n)
        s += h[(size_t)sj[n] * 256 + c];
    g_rootsum[(size_t)b * 256 + c] = s;
}

__global__ void root_out(const float* __restrict__ Woh, const float* __restrict__ bo,
                         const int* __restrict__ rwid, float* __restrict__ out)
{
    const int b = blockIdx.x;
    const int n = threadIdx.x;
    const float* a = &g_rootsum[(size_t)b * 256];
    float acc = 0.f;
#pragma unroll 8
    for (int k = 0; k < 256; ++k)
        acc += a[k] * Woh[(size_t)k * 256 + n];
    const int xid = rwid[b];
    float v = g_Eo[(size_t)xid * 256 + n] + bo[n] + acc;
    out[(size_t)b * 256 + n] = fmaxf(v, 0.0f);
}

// ---------------- launch ------------------------------------------------------
extern "C" void kernel_launch(void* const* d_in, const int* in_sizes, int n_in,
                              void* d_out, int out_size)
{
    const int*   x_ids    = (const int*)  d_in[0];   // [T,E]
    const int*   nei_idx  = (const int*)  d_in[1];   // [T,E,NB]
    const int*   root_wid = (const int*)  d_in[2];   // [B]
    const int*   root_nei = (const int*)  d_in[3];   // [B,NB]
    const float* emb      = (const float*)d_in[4];   // [V,H]
    const float* Wz       = (const float*)d_in[5];   // [2H,H]
    const float* bz       = (const float*)d_in[6];
    const float* Wr       = (const float*)d_in[7];   // [H,H]
    const float* Ur       = (const float*)d_in[8];   // [H,H]
    const float* bur      = (const float*)d_in[9];
    const float* Wh       = (const float*)d_in[10];  // [2H,H]
    const float* bh       = (const float*)d_in[11];
    const float* Wo       = (const float*)d_in[12];  // [2H,H]
    const float* bo       = (const float*)d_in[13];

    float* out  = (float*)d_out;
    float* h    = out;                               // [(1+M), H]
    float* rvec = out + (size_t)(M_ + 1) * H_;       // [B, H]

    float *p_hU, *p_Ez, *p_Er, *p_Eh, *p_Eo;
    cudaGetSymbolAddress((void**)&p_hU, g_hU);
    cudaGetSymbolAddress((void**)&p_Ez, g_Ez);
    cudaGetSymbolAddress((void**)&p_Er, g_Er);
    cudaGetSymbolAddress((void**)&p_Eh, g_Eh);
    cudaGetSymbolAddress((void**)&p_Eo, g_Eo);

    init_zero<<<1, 256>>>(h);

    // one-time embedding projections: [800,256] @ [256,256]
    dim3 gpre(4, (V_ + 63) / 64);
    gemm256<<<gpre, 256>>>(emb, Wz,            p_Ez, V_);   // Wz_x = rows 0..255
    gemm256<<<gpre, 256>>>(emb, Wr,            p_Er, V_);
    gemm256<<<gpre, 256>>>(emb, Wh,            p_Eh, V_);   // Wh_x = rows 0..255
    gemm256<<<gpre, 256>>>(emb, Wo,            p_Eo, V_);   // Wo_x = rows 0..255

    dim3 gmain(4, E_ / 64);
    for (int t = 0; t < T_; ++t) {
        gather_step<<<E_, 256>>>(h, nei_idx + (size_t)t * E_ * NB_,
                                 x_ids + (size_t)t * E_, bur);
        zpre_gemm<<<gmain, 256>>>(Wz + (size_t)H_ * H_, Wh + (size_t)H_ * H_,
                                  bz, bh, x_ids + (size_t)t * E_,
                                  h + (size_t)(1 + t * E_) * H_);
        gemm256<<<gmain, 256>>>(h + (size_t)(1 + t * E_) * H_, Ur,
                                p_hU + (size_t)(1 + t * E_) * H_, E_);
    }

    root_gather<<<B_, 256>>>(h, root_nei);
    root_out<<<B_, 256>>>(Wo + (size_t)H_ * H_, bo, root_wid, rvec);
}

// round 2
// speedup vs baseline: 2.1416x; 2.1416x over previous
#include <cuda_runtime.h>
#include <cuda_bf16.h>
#include <math.h>
#include <stdint.h>

#define T_  12
#define E_  8192
#define H_  256
#define V_  800
#define B_  256
#define NB_ 8
#define M_  (T_*E_)   // 98304 messages; h has 1+M rows (row 0 = pad)

// ---------------- scratch (static device arrays; no allocs allowed) ----------
__device__ float g_hU[(size_t)(M_+1)*H_];   // h @ Ur (fp32), incrementally extended
__device__ float g_sumh[(size_t)E_*H_];     // per-step sum of neighbor h (fp32, epilogue)
__device__ float g_Ez[(size_t)V_*H_];       // embedding @ Wz[0:H]
__device__ float g_Er[(size_t)V_*H_];       // embedding @ Wr
__device__ float g_Eh[(size_t)V_*H_];       // embedding @ Wh[0:H]
__device__ float g_Eo[(size_t)V_*H_];       // embedding @ Wo[0:H]
__device__ float g_rootsum[(size_t)B_*H_];

// bf16 hi/lo split operands for MMA GEMMs
__device__ __nv_bfloat16 g_sh_hi[(size_t)E_*H_], g_sh_lo[(size_t)E_*H_];
__device__ __nv_bfloat16 g_sg_hi[(size_t)E_*H_], g_sg_lo[(size_t)E_*H_];
__device__ __nv_bfloat16 g_hA_hi[(size_t)E_*H_], g_hA_lo[(size_t)E_*H_];
__device__ __nv_bfloat16 g_Wzh_hi[H_*H_], g_Wzh_lo[H_*H_];
__device__ __nv_bfloat16 g_Whh_hi[H_*H_], g_Whh_lo[H_*H_];
__device__ __nv_bfloat16 g_Ur_hi [H_*H_], g_Ur_lo [H_*H_];

__device__ __forceinline__ float sigf(float x) { return 1.0f / (1.0f + __expf(-x)); }

// ---------------- PTX helpers -------------------------------------------------
__device__ __forceinline__ uint32_t smem_u32(const void* p) {
    return (uint32_t)__cvta_generic_to_shared(p);
}
__device__ __forceinline__ void ldsm4(uint32_t* r, uint32_t a) {
    asm volatile("ldmatrix.sync.aligned.m8n8.x4.shared.b16 {%0,%1,%2,%3},[%4];\n"
                 : "=r"(r[0]), "=r"(r[1]), "=r"(r[2]), "=r"(r[3]) : "r"(a));
}
__device__ __forceinline__ void ldsm4t(uint32_t* r, uint32_t a) {
    asm volatile("ldmatrix.sync.aligned.m8n8.x4.trans.shared.b16 {%0,%1,%2,%3},[%4];\n"
                 : "=r"(r[0]), "=r"(r[1]), "=r"(r[2]), "=r"(r[3]) : "r"(a));
}
__device__ __forceinline__ void mma16816(float* d, const uint32_t* a, const uint32_t* b) {
    asm volatile("mma.sync.aligned.m16n8k16.row.col.f32.bf16.bf16.f32 "
                 "{%0,%1,%2,%3},{%4,%5,%6,%7},{%8,%9},{%0,%1,%2,%3};\n"
                 : "+f"(d[0]), "+f"(d[1]), "+f"(d[2]), "+f"(d[3])
                 : "r"(a[0]), "r"(a[1]), "r"(a[2]), "r"(a[3]), "r"(b[0]), "r"(b[1]));
}

// ---------------- init --------------------------------------------------------
__global__ void init_zero(float* __restrict__ h)
{
    int c = threadIdx.x;
    h[c]    = 0.0f;
    g_hU[c] = 0.0f;
}

// ---------------- fp32 weight -> bf16 hi/lo split -----------------------------
__global__ void split_w(const float* __restrict__ W,
                        __nv_bfloat16* __restrict__ hi, __nv_bfloat16* __restrict__ lo)
{
    int i = blockIdx.x * 256 + threadIdx.x;   // 65536 elements
    float v = W[i];
    __nv_bfloat16 h = __float2bfloat16(v);
    hi[i] = h;
    lo[i] = __float2bfloat16(v - __bfloat162float(h));
}

// ---------------- fp32 tiled GEMM (preamble only): C[M,256]=A[M,256]@B[256,256]
__global__ void gemm256(const float* __restrict__ A, const float* __restrict__ Bw,
                        float* __restrict__ C, int Mrows)
{
    __shared__ float As[16][64];
    __shared__ float Bs[16][64];
    const int tid = threadIdx.x;
    const int tx = tid & 15, ty = tid >> 4;
    const int rowBase = blockIdx.y * 64;
    const int colBase = blockIdx.x * 64;
    const int lm  = tid >> 2;
    const int lk  = (tid & 3) * 4;
    const int blk = tid >> 4;
    const int bln = (tid & 15) * 4;
    float acc[4][4] = {};
    for (int kb = 0; kb < 256; kb += 16) {
        int ar = rowBase + lm;
        float4 av = make_float4(0.f, 0.f, 0.f, 0.f);
        if (ar < Mrows)
            av = *reinterpret_cast<const float4*>(&A[(size_t)ar * 256 + kb + lk]);
        As[lk + 0][lm] = av.x; As[lk + 1][lm] = av.y;
        As[lk + 2][lm] = av.z; As[lk + 3][lm] = av.w;
        float4 bv = *reinterpret_cast<const float4*>(&Bw[(size_t)(kb + blk) * 256 + colBase + bln]);
        *reinterpret_cast<float4*>(&Bs[blk][bln]) = bv;
        __syncthreads();
#pragma unroll
        for (int k = 0; k < 16; ++k) {
            float4 a4 = *reinterpret_cast<const float4*>(&As[k][ty * 4]);
            float4 b4 = *reinterpret_cast<const float4*>(&Bs[k][tx * 4]);
            float aa[4] = {a4.x, a4.y, a4.z, a4.w};
            float bb[4] = {b4.x, b4.y, b4.z, b4.w};
#pragma unroll
            for (int i = 0; i < 4; ++i)
#pragma unroll
                for (int j = 0; j < 4; ++j)
                    acc[i][j] += aa[i] * bb[j];
        }
        __syncthreads();
    }
#pragma unroll
    for (int i = 0; i < 4; ++i) {
        int r = rowBase + ty * 4 + i;
        if (r < Mrows)
            *reinterpret_cast<float4*>(&C[(size_t)r * 256 + colBase + tx * 4]) =
                make_float4(acc[i][0], acc[i][1], acc[i][2], acc[i][3]);
    }
}

// ---------------- per-step gather: sum_h (fp32 + bf16 hi/lo), sum_gated (bf16) -
__global__ void gather_step(const float* __restrict__ h,
                            const int*   __restrict__ nei,
                            const int*   __restrict__ xids,
                            const float* __restrict__ bur)
{
    const int msg = blockIdx.x * 4 + (threadIdx.x >> 6);
    const int c4  = threadIdx.x & 63;          // float4 chunk within H

    const int xid = xids[msg];
    const float4 bu = reinterpret_cast<const float4*>(bur)[c4];
    const float4 er = reinterpret_cast<const float4*>(&g_Er[(size_t)xid * H_])[c4];
    const float bx = er.x + bu.x, by = er.y + bu.y, bz2 = er.z + bu.z, bw = er.w + bu.w;

    float4 sh = make_float4(0.f, 0.f, 0.f, 0.f);
    float4 sg = make_float4(0.f, 0.f, 0.f, 0.f);
#pragma unroll
    for (int n = 0; n < NB_; ++n) {
        const int j = nei[msg * NB_ + n];
        const float4 hv = reinterpret_cast<const float4*>(h)[(size_t)j * 64 + c4];
        const float4 uv = reinterpret_cast<const float4*>(g_hU)[(size_t)j * 64 + c4];
        sh.x += hv.x; sh.y += hv.y; sh.z += hv.z; sh.w += hv.w;
        sg.x += sigf(bx  + uv.x) * hv.x;
        sg.y += sigf(by  + uv.y) * hv.y;
        sg.z += sigf(bz2 + uv.z) * hv.z;
        sg.w += sigf(bw  + uv.w) * hv.w;
    }
    const size_t o4 = (size_t)msg * 64 + c4;
    reinterpret_cast<float4*>(g_sumh)[o4] = sh;

    // split to bf16 hi/lo (8B stores)
    {
        __nv_bfloat16 h0 = __float2bfloat16(sh.x), h1 = __float2bfloat16(sh.y),
                      h2 = __float2bfloat16(sh.z), h3 = __float2bfloat16(sh.w);
        __nv_bfloat162 a, b; a.x = h0; a.y = h1; b.x = h2; b.y = h3;
        uint2 u; u.x = *reinterpret_cast<uint32_t*>(&a); u.y = *reinterpret_cast<uint32_t*>(&b);
        reinterpret_cast<uint2*>(g_sh_hi)[o4] = u;
        __nv_bfloat162 c, d;
        c.x = __float2bfloat16(sh.x - __bfloat162float(h0));
        c.y = __float2bfloat16(sh.y - __bfloat162float(h1));
        d.x = __float2bfloat16(sh.z - __bfloat162float(h2));
        d.y = __float2bfloat16(sh.w - __bfloat162float(h3));
        uint2 v; v.x = *reinterpret_cast<uint32_t*>(&c); v.y = *reinterpret_cast<uint32_t*>(&d);
        reinterpret_cast<uint2*>(g_sh_lo)[o4] = v;
    }
    {
        __nv_bfloat16 h0 = __float2bfloat16(sg.x), h1 = __float2bfloat16(sg.y),
                      h2 = __float2bfloat16(sg.z), h3 = __float2bfloat16(sg.w);
        __nv_bfloat162 a, b; a.x = h0; a.y = h1; b.x = h2; b.y = h3;
        uint2 u; u.x = *reinterpret_cast<uint32_t*>(&a); u.y = *reinterpret_cast<uint32_t*>(&b);
        reinterpret_cast<uint2*>(g_sg_hi)[o4] = u;
        __nv_bfloat162 c, d;
        c.x = __float2bfloat16(sg.x - __bfloat162float(h0));
        c.y = __float2bfloat16(sg.y - __bfloat162float(h1));
        d.x = __float2bfloat16(sg.z - __bfloat162float(h2));
        d.y = __float2bfloat16(sg.w - __bfloat162float(h3));
        uint2 v; v.x = *reinterpret_cast<uint32_t*>(&c); v.y = *reinterpret_cast<uint32_t*>(&d);
        reinterpret_cast<uint2*>(g_sg_lo)[o4] = v;
    }
}

// ---------------- MMA GEMM pass: acc += A(hi+lo) @ B(hi+lo), 3-term bf16 ------
// BM=64, BN=128, BK=32; 256 threads = 8 warps (2 M x 4 N), warp tile 32x32.
#define A_STRIDE 40    // 32 + 8 pad (bf16 elements)
#define B_STRIDE 136   // 128 + 8 pad

__device__ __forceinline__ void gemm_pass(
    const __nv_bfloat16* __restrict__ Ahi, const __nv_bfloat16* __restrict__ Alo,
    const __nv_bfloat16* __restrict__ Bhi, const __nv_bfloat16* __restrict__ Blo,
    int rowBase, int colBase, float acc[2][4][4],
    __nv_bfloat16* sAhi, __nv_bfloat16* sAlo,
    __nv_bfloat16* sBhi, __nv_bfloat16* sBlo)
{
    const int tid  = threadIdx.x;
    const int lane = tid & 31;
    const int wid  = tid >> 5;
    const int warp_m = wid & 1;      // 2 warps along M
    const int warp_n = wid >> 1;     // 4 warps along N

    const int arow = tid >> 2;            // 0..63
    const int ak   = (tid & 3) * 8;       // 0,8,16,24
    const int brow = tid >> 3;            // 0..31
    const int bcol = (tid & 7) * 8;       // 0..56

    const uint32_t bAhi = smem_u32(sAhi), bAlo = smem_u32(sAlo);
    const uint32_t bBhi = smem_u32(sBhi), bBlo = smem_u32(sBlo);

    for (int kb = 0; kb < 256; kb += 32) {
        __syncthreads();
        *reinterpret_cast<uint4*>(&sAhi[arow * A_STRIDE + ak]) =
            *reinterpret_cast<const uint4*>(&Ahi[(size_t)(rowBase + arow) * 256 + kb + ak]);
        *reinterpret_cast<uint4*>(&sAlo[arow * A_STRIDE + ak]) =
            *reinterpret_cast<const uint4*>(&Alo[(size_t)(rowBase + arow) * 256 + kb + ak]);
        *reinterpret_cast<uint4*>(&sBhi[brow * B_STRIDE + bcol]) =
            *reinterpret_cast<const uint4*>(&Bhi[(size_t)(kb + brow) * 256 + colBase + bcol]);
        *reinterpret_cast<uint4*>(&sBhi[brow * B_STRIDE + bcol + 64]) =
            *reinterpret_cast<const uint4*>(&Bhi[(size_t)(kb + brow) * 256 + colBase + bcol + 64]);
        *reinterpret_cast<uint4*>(&sBlo[brow * B_STRIDE + bcol]) =
            *reinterpret_cast<const uint4*>(&Blo[(size_t)(kb + brow) * 256 + colBase + bcol]);
        *reinterpret_cast<uint4*>(&sBlo[brow * B_STRIDE + bcol + 64]) =
            *reinterpret_cast<const uint4*>(&Blo[(size_t)(kb + brow) * 256 + colBase + bcol + 64]);
        __syncthreads();

#pragma unroll
        for (int ks = 0; ks < 32; ks += 16) {
            uint32_t ahi[2][4], alo[2][4];
#pragma unroll
            for (int mt = 0; mt < 2; ++mt) {
                const int el = (warp_m * 32 + mt * 16 + (lane & 15)) * A_STRIDE
                             + ks + (lane >> 4) * 8;
                ldsm4(ahi[mt], bAhi + el * 2);
                ldsm4(alo[mt], bAlo + el * 2);
            }
#pragma unroll
            for (int np = 0; np < 2; ++np) {
                const int n0 = warp_n * 32 + np * 16;
                const int el = (ks + (lane & 7) + ((lane >> 3) & 1) * 8) * B_STRIDE
                             + n0 + (lane >> 4) * 8;
                uint32_t bh[4], bl[4];
                ldsm4t(bh, bBhi + el * 2);
                ldsm4t(bl, bBlo + el * 2);
#pragma unroll
                for (int mt = 0; mt < 2; ++mt) {
#pragma unroll
                    for (int s = 0; s < 2; ++s) {
                        float* d = acc[mt][np * 2 + s];
                        mma16816(d, ahi[mt], &bh[2 * s]);
                        mma16816(d, ahi[mt], &bl[2 * s]);
                        mma16816(d, alo[mt], &bh[2 * s]);
                    }
                }
            }
        }
    }
}

// ---------------- zpre: dual MMA GEMM + GRU epilogue --------------------------
__global__ void __launch_bounds__(256) zpre_mma(
    const float* __restrict__ bz, const float* __restrict__ bh,
    const int*   __restrict__ xids, float* __restrict__ hout)
{
    __shared__ __nv_bfloat16 sAhi[64 * A_STRIDE], sAlo[64 * A_STRIDE];
    __shared__ __nv_bfloat16 sBhi[32 * B_STRIDE], sBlo[32 * B_STRIDE];

    const int rowBase = blockIdx.y * 64;
    const int colBase = blockIdx.x * 128;

    float acc1[2][4][4] = {};
    float acc2[2][4][4] = {};
    gemm_pass(g_sh_hi, g_sh_lo, g_Wzh_hi, g_Wzh_lo, rowBase, colBase, acc1,
              sAhi, sAlo, sBhi, sBlo);
    gemm_pass(g_sg_hi, g_sg_lo, g_Whh_hi, g_Whh_lo, rowBase, colBase, acc2,
              sAhi, sAlo, sBhi, sBlo);

    const int lane = threadIdx.x & 31;
    const int wid  = threadIdx.x >> 5;
    const int warp_m = wid & 1, warp_n = wid >> 1;

#pragma unroll
    for (int mt = 0; mt < 2; ++mt) {
#pragma unroll
        for (int nt = 0; nt < 4; ++nt) {
            const int col = colBase + warp_n * 32 + nt * 8 + (lane & 3) * 2;
#pragma unroll
            for (int half = 0; half < 2; ++half) {
                const int r = rowBase + warp_m * 32 + mt * 16 + (lane >> 2) + half * 8;
                const float a1x = acc1[mt][nt][half * 2 + 0];
                const float a1y = acc1[mt][nt][half * 2 + 1];
                const float a2x = acc2[mt][nt][half * 2 + 0];
                const float a2y = acc2[mt][nt][half * 2 + 1];
                const int xid = xids[r];
                const float2 ez  = *reinterpret_cast<const float2*>(&g_Ez[(size_t)xid * H_ + col]);
                const float2 eh  = *reinterpret_cast<const float2*>(&g_Eh[(size_t)xid * H_ + col]);
                const float2 bzv = *reinterpret_cast<const float2*>(&bz[col]);
                const float2 bhv = *reinterpret_cast<const float2*>(&bh[col]);
                const float2 sh  = *reinterpret_cast<const float2*>(&g_sumh[(size_t)r * H_ + col]);
                const float z0 = sigf(ez.x + bzv.x + a1x);
                const float z1 = sigf(ez.y + bzv.y + a1y);
                const float p0 = tanhf(eh.x + bhv.x + a2x);
                const float p1 = tanhf(eh.y + bhv.y + a2y);
                const float o0 = (1.0f - z0) * sh.x + z0 * p0;
                const float o1 = (1.0f - z1) * sh.y + z1 * p1;
                *reinterpret_cast<float2*>(&hout[(size_t)r * H_ + col]) = make_float2(o0, o1);
                __nv_bfloat162 hp; hp.x = __float2bfloat16(o0); hp.y = __float2bfloat16(o1);
                *reinterpret_cast<__nv_bfloat162*>(&g_hA_hi[(size_t)r * H_ + col]) = hp;
                __nv_bfloat162 lp;
                lp.x = __float2bfloat16(o0 - __bfloat162float(hp.x));
                lp.y = __float2bfloat16(o1 - __bfloat162float(hp.y));
                *reinterpret_cast<__nv_bfloat162*>(&g_hA_lo[(size_t)r * H_ + col]) = lp;
            }
        }
    }
}

// ---------------- Ur MMA GEMM: g_hU rows = new_h @ Ur -------------------------
__global__ void __launch_bounds__(256) gemmUr_mma(float* __restrict__ C)
{
    __shared__ __nv_bfloat16 sAhi[64 * A_STRIDE], sAlo[64 * A_STRIDE];
    __shared__ __nv_bfloat16 sBhi[32 * B_STRIDE], sBlo[32 * B_STRIDE];

    const int rowBase = blockIdx.y * 64;
    const int colBase = blockIdx.x * 128;

    float acc[2][4][4] = {};
    gemm_pass(g_hA_hi, g_hA_lo, g_Ur_hi, g_Ur_lo, rowBase, colBase, acc,
              sAhi, sAlo, sBhi, sBlo);

    const int lane = threadIdx.x & 31;
    const int wid  = threadIdx.x >> 5;
    const int warp_m = wid & 1, warp_n = wid >> 1;

#pragma unroll
    for (int mt = 0; mt < 2; ++mt) {
#pragma unroll
        for (int nt = 0; nt < 4; ++nt) {
            const int col = colBase + warp_n * 32 + nt * 8 + (lane & 3) * 2;
            const int r0  = rowBase + warp_m * 32 + mt * 16 + (lane >> 2);
            *reinterpret_cast<float2*>(&C[(size_t)r0 * H_ + col]) =
                make_float2(acc[mt][nt][0], acc[mt][nt][1]);
            *reinterpret_cast<float2*>(&C[(size_t)(r0 + 8) * H_ + col]) =
                make_float2(acc[mt][nt][2], acc[mt][nt][3]);
        }
    }
}

// ---------------- root aggregate ---------------------------------------------
__global__ void root_gather(const float* __restrict__ h, const int* __restrict__ rnei)
{
    const int b = blockIdx.x;
    const int c = threadIdx.x;
    __shared__ int sj[NB_];
    if (c < NB_) sj[c] = rnei[b * NB_ + c];
    __syncthreads();
    float s = 0.f;
#pragma unroll
    for (int n = 0; n < NB_; ++n)
        s += h[(size_t)sj[n] * 256 + c];
    g_rootsum[(size_t)b * 256 + c] = s;
}

__global__ void root_out(const float* __restrict__ Woh, const float* __restrict__ bo,
                         const int* __restrict__ rwid, float* __restrict__ out)
{
    const int b = blockIdx.x;
    const int n = threadIdx.x;
    const float* a = &g_rootsum[(size_t)b * 256];
    float acc = 0.f;
#pragma unroll 8
    for (int k = 0; k < 256; ++k)
        acc += a[k] * Woh[(size_t)k * 256 + n];
    const int xid = rwid[b];
    float v = g_Eo[(size_t)xid * 256 + n] + bo[n] + acc;
    out[(size_t)b * 256 + n] = fmaxf(v, 0.0f);
}

// ---------------- launch ------------------------------------------------------
extern "C" void kernel_launch(void* const* d_in, const int* in_sizes, int n_in,
                              void* d_out, int out_size)
{
    const int*   x_ids    = (const int*)  d_in[0];
    const int*   nei_idx  = (const int*)  d_in[1];
    const int*   root_wid = (const int*)  d_in[2];
    const int*   root_nei = (const int*)  d_in[3];
    const float* emb      = (const float*)d_in[4];
    const float* Wz       = (const float*)d_in[5];
    const float* bz       = (const float*)d_in[6];
    const float* Wr       = (const float*)d_in[7];
    const float* Ur       = (const float*)d_in[8];
    const float* bur      = (const float*)d_in[9];
    const float* Wh       = (const float*)d_in[10];
    const float* bh       = (const float*)d_in[11];
    const float* Wo       = (const float*)d_in[12];
    const float* bo       = (const float*)d_in[13];

    float* out  = (float*)d_out;
    float* h    = out;
    float* rvec = out + (size_t)(M_ + 1) * H_;

    float *p_hU, *p_Ez, *p_Er, *p_Eh, *p_Eo;
    cudaGetSymbolAddress((void**)&p_hU, g_hU);
    cudaGetSymbolAddress((void**)&p_Ez, g_Ez);
    cudaGetSymbolAddress((void**)&p_Er, g_Er);
    cudaGetSymbolAddress((void**)&p_Eh, g_Eh);
    cudaGetSymbolAddress((void**)&p_Eo, g_Eo);
    __nv_bfloat16 *p_Wzh_hi, *p_Wzh_lo, *p_Whh_hi, *p_Whh_lo, *p_Ur_hi, *p_Ur_lo;
    cudaGetSymbolAddress((void**)&p_Wzh_hi, g_Wzh_hi);
    cudaGetSymbolAddress((void**)&p_Wzh_lo, g_Wzh_lo);
    cudaGetSymbolAddress((void**)&p_Whh_hi, g_Whh_hi);
    cudaGetSymbolAddress((void**)&p_Whh_lo, g_Whh_lo);
    cudaGetSymbolAddress((void**)&p_Ur_hi,  g_Ur_hi);
    cudaGetSymbolAddress((void**)&p_Ur_lo,  g_Ur_lo);

    init_zero<<<1, 256>>>(h);

    // one-time embedding projections (fp32) + weight splits (bf16 hi/lo)
    dim3 gpre(4, (V_ + 63) / 64);
    gemm256<<<gpre, 256>>>(emb, Wz, p_Ez, V_);
    gemm256<<<gpre, 256>>>(emb, Wr, p_Er, V_);
    gemm256<<<gpre, 256>>>(emb, Wh, p_Eh, V_);
    gemm256<<<gpre, 256>>>(emb, Wo, p_Eo, V_);
    split_w<<<256, 256>>>(Wz + (size_t)H_ * H_, p_Wzh_hi, p_Wzh_lo);
    split_w<<<256, 256>>>(Wh + (size_t)H_ * H_, p_Whh_hi, p_Whh_lo);
    split_w<<<256, 256>>>(Ur,                   p_Ur_hi,  p_Ur_lo);

    dim3 gmma(2, E_ / 64);   // (N/128, M/64)
    for (int t = 0; t < T_; ++t) {
        gather_step<<<E_ / 4, 256>>>(h, nei_idx + (size_t)t * E_ * NB_,
                                     x_ids + (size_t)t * E_, bur);
        zpre_mma<<<gmma, 256>>>(bz, bh, x_ids + (size_t)t * E_,
                                h + (size_t)(1 + t * E_) * H_);
        gemmUr_mma<<<gmma, 256>>>(p_hU + (size_t)(1 + t * E_) * H_);
    }

    root_gather<<<B_, 256>>>(h, root_nei);
    root_out<<<B_, 256>>>(Wo + (size_t)H_ * H_, bo, root_wid, rvec);
}